// round 16
// baseline (speedup 1.0000x reference)
#include <cuda_runtime.h>
#include <cuda_bf16.h>
#include <cuda_fp16.h>
#include <math.h>
#include <stdint.h>

typedef unsigned int u32;
typedef unsigned long long u64;

#define NN 10000
#define NPAD2 10240           /* padded degree array for int2 scan loads */
#define EE 160000
#define DD 512
#define ND (NN * DD)          /* 5,120,000 */
#define MPAD 10112            /* 79 * 128 */

// ---------------- scratch (static device globals: allocation-free) ----------
__device__ __align__(16) __half g_y[ND];               // y = z @ W (fp16)
__device__ __align__(16) __half g_a[MPAD * DD];        // GEMM input, fp16 (padded rows stay 0)
__device__ __align__(16) __half g_wthi[3 * DD * DD];   // W^T fp16 hi, per layer
__device__ __align__(16) __half g_wtlo[3 * DD * DD];   // W^T fp16 lo (residual)
__device__ float g_ido[NN];
__device__ float g_idi[NN];
__device__ int   g_dego[NN];
__device__ __align__(16) int g_degi[NPAD2];
__device__ int   g_roff[NN + 1];
__device__ int   g_cur[NN];
__device__ int   g_esrc[EE];
__device__ float g_eew[EE];

// ---------------- JAX-compatible threefry2x32 (partitionable) ---------------
struct U2 { u32 a, b; };
constexpr u32 rotl_c(u32 v, int r) { return (v << r) | (v >> (32 - r)); }
constexpr U2 tf_host(u32 k0, u32 k1, u32 x0, u32 x1) {
    u32 ks2 = 0x1BD11BDAu ^ k0 ^ k1;
    x0 += k0; x1 += k1;
    const int R0[4] = {13, 15, 26, 6};
    const int R1[4] = {17, 29, 16, 24};
    for (int g = 0; g < 5; ++g) {
        for (int i = 0; i < 4; ++i) {
            int r = (g & 1) ? R1[i] : R0[i];
            x0 += x1; x1 = rotl_c(x1, r); x1 ^= x0;
        }
        switch (g) {
            case 0: x0 += k1;  x1 += ks2 + 1u; break;
            case 1: x0 += ks2; x1 += k0  + 2u; break;
            case 2: x0 += k0;  x1 += k1  + 3u; break;
            case 3: x0 += k1;  x1 += ks2 + 4u; break;
            default: x0 += ks2; x1 += k0 + 5u; break;
        }
    }
    return U2{x0, x1};
}
constexpr U2 DK0 = tf_host(0u, 42u, 0u, 0u);
constexpr U2 DK1 = tf_host(0u, 42u, 0u, 1u);
constexpr U2 DK2 = tf_host(0u, 42u, 0u, 2u);

__device__ __forceinline__ void tf_dev(u32 k0, u32 k1, u32& x0, u32& x1) {
    u32 ks2 = 0x1BD11BDAu ^ k0 ^ k1;
    x0 += k0; x1 += k1;
#define TFR(r) { x0 += x1; x1 = (x1 << (r)) | (x1 >> (32 - (r))); x1 ^= x0; }
    TFR(13) TFR(15) TFR(26) TFR(6)   x0 += k1;  x1 += ks2 + 1u;
    TFR(17) TFR(29) TFR(16) TFR(24)  x0 += ks2; x1 += k0  + 2u;
    TFR(13) TFR(15) TFR(26) TFR(6)   x0 += k0;  x1 += k1  + 3u;
    TFR(17) TFR(29) TFR(16) TFR(24)  x0 += k1;  x1 += ks2 + 4u;
    TFR(13) TFR(15) TFR(26) TFR(6)   x0 += ks2; x1 += k0  + 5u;
#undef TFR
}

__device__ __forceinline__ bool tf_keep(u32 k0, u32 k1, u32 j) {
    u32 x0 = 0u, x1 = j;
    tf_dev(k0, k1, x0, x1);
    u32 bits = x0 ^ x1;
    float u = __uint_as_float((bits >> 9) | 0x3f800000u) - 1.0f;
    return u < 0.8f;
}

// pack 4 floats -> 4 fp16 in a uint2
__device__ __forceinline__ uint2 pack_h4(const float* o) {
    __half2 p01 = __floats2half2_rn(o[0], o[1]);
    __half2 p23 = __floats2half2_rn(o[2], o[3]);
    uint2 u;
    u.x = *(u32*)&p01; u.y = *(u32*)&p23;
    return u;
}

// ---------------- mma.sync helpers (family-compatible, no 'a' features) -----
__device__ __forceinline__ u32 smem_u32(const void* p) {
    u32 a;
    asm("{ .reg .u64 t; cvta.to.shared.u64 t, %1; cvt.u32.u64 %0, t; }" : "=r"(a) : "l"(p));
    return a;
}
__device__ __forceinline__ void ldsm4(u32& r0, u32& r1, u32& r2, u32& r3, u32 addr) {
    asm volatile("ldmatrix.sync.aligned.m8n8.x4.shared.b16 {%0,%1,%2,%3}, [%4];"
                 : "=r"(r0), "=r"(r1), "=r"(r2), "=r"(r3) : "r"(addr));
}
__device__ __forceinline__ void mma_fp16(float& c0, float& c1, float& c2, float& c3,
                                         u32 a0, u32 a1, u32 a2, u32 a3,
                                         u32 b0, u32 b1) {
    asm volatile(
        "mma.sync.aligned.m16n8k16.row.col.f32.f16.f16.f32 "
        "{%0,%1,%2,%3}, {%4,%5,%6,%7}, {%8,%9}, {%0,%1,%2,%3};"
        : "+f"(c0), "+f"(c1), "+f"(c2), "+f"(c3)
        : "r"(a0), "r"(a1), "r"(a2), "r"(a3), "r"(b0), "r"(b1));
}
__device__ __forceinline__ void cp16(u32 smem_dst, const void* gptr) {
    asm volatile("cp.async.cg.shared.global [%0], [%1], 16;"
                 :: "r"(smem_dst), "l"(gptr) : "memory");
}

// ---------------- degree + CSR build ---------------------------------------
__global__ void k_zero_deg() {
    int i = blockIdx.x * blockDim.x + threadIdx.x;
    if (i < NN) g_dego[i] = 0;
    if (i < NPAD2) g_degi[i] = 0;
}

// fused: degree count (blocks 0..624) + weight transpose/split (blocks 625..1392)
#define CNT_BLOCKS 625
__global__ void k_setup(const int* __restrict__ src, const int* __restrict__ dst,
                        const float* __restrict__ W0, const float* __restrict__ W1,
                        const float* __restrict__ W2) {
    if (blockIdx.x < CNT_BLOCKS) {
        int e = blockIdx.x * blockDim.x + threadIdx.x;
        if (e < EE) {
            atomicAdd(&g_dego[src[e]], 1);
            atomicAdd(&g_degi[dst[e]], 1);
        }
        return;
    }
    __shared__ float tile[32][33];
    const int bid = blockIdx.x - CNT_BLOCKS;
    const int L = bid >> 8;                    // 0..2
    const int tix = bid & 255;
    const int bx = (tix & 15) * 32, by = (tix >> 4) * 32;
    const float* __restrict__ W = (L == 0) ? W0 : ((L == 1) ? W1 : W2);
    __half* __restrict__ TH = g_wthi + (size_t)L * DD * DD;
    __half* __restrict__ TL = g_wtlo + (size_t)L * DD * DD;
    const int tx = threadIdx.x & 31, ty = threadIdx.x >> 5;   // 32 x 8
#pragma unroll
    for (int i = 0; i < 32; i += 8)
        tile[ty + i][tx] = W[(size_t)(by + ty + i) * DD + bx + tx];
    __syncthreads();
#pragma unroll
    for (int i = 0; i < 32; i += 8) {
        float v = tile[tx][ty + i];
        __half h = __float2half_rn(v);
        float lo = v - __half2float(h);
        TH[(size_t)(bx + ty + i) * DD + by + tx] = h;
        TL[(size_t)(bx + ty + i) * DD + by + tx] = __float2half_rn(lo);
    }
}

// pure exclusive prefix sum of g_degi -> g_roff / g_cur
__global__ void k_scan() {
    const int t = threadIdx.x;
    const int2* p = (const int2*)g_degi + t * 5;
    int2 d0 = p[0], d1 = p[1], d2 = p[2], d3 = p[3], d4 = p[4];
    int vals[10] = {d0.x, d0.y, d1.x, d1.y, d2.x, d2.y, d3.x, d3.y, d4.x, d4.y};
    int loc[10], sum = 0;
#pragma unroll
    for (int i = 0; i < 10; ++i) { loc[i] = sum; sum += vals[i]; }
    int lane = t & 31, w = t >> 5;
    int inc = sum;
#pragma unroll
    for (int o = 1; o < 32; o <<= 1) {
        int x = __shfl_up_sync(0xFFFFFFFFu, inc, o);
        if (lane >= o) inc += x;
    }
    __shared__ int ws[32];
    if (lane == 31) ws[w] = inc;
    __syncthreads();
    if (w == 0) {
        int x = ws[lane];
#pragma unroll
        for (int o = 1; o < 32; o <<= 1) {
            int y = __shfl_up_sync(0xFFFFFFFFu, x, o);
            if (lane >= o) x += y;
        }
        ws[lane] = x;
    }
    __syncthreads();
    int excl = inc - sum + (w ? ws[w - 1] : 0);
#pragma unroll
    for (int i = 0; i < 10; ++i) {
        int idx = t * 10 + i;
        if (idx < NN) { int o = excl + loc[i]; g_roff[idx] = o; g_cur[idx] = o; }
    }
    if (t == 0) g_roff[NN] = ws[31];
}

// CSR fill + grid-wide rsqrt of degrees
__global__ void k_fill(const int* __restrict__ src, const int* __restrict__ dst,
                       const float* __restrict__ ew) {
    int e = blockIdx.x * blockDim.x + threadIdx.x;
    if (e < NN) {
        g_ido[e] = rsqrtf(fmaxf((float)g_dego[e], 1.0f));
        g_idi[e] = rsqrtf(fmaxf((float)g_degi[e], 1.0f));
    }
    if (e < EE) {
        int pos = atomicAdd(&g_cur[dst[e]], 1);
        g_esrc[pos] = src[e];
        g_eew[pos] = ew[e];
    }
}

// ---------------- layer-0: dropout(h)*do^-0.5 -> fp16 -----------------------
__global__ void k_drop(const float* __restrict__ xin, u32 k0, u32 k1) {
    int q = blockIdx.x * blockDim.x + threadIdx.x;
    if (q >= ND / 4) return;
    int j0 = q << 2;
    int row = j0 >> 9, c = j0 & 511;
    float4 v = *(const float4*)(xin + j0);
    float s = rsqrtf(fmaxf((float)g_dego[row], 1.0f)) * 1.25f;
    float o[4] = {v.x, v.y, v.z, v.w};
#pragma unroll
    for (int t = 0; t < 4; ++t)
        o[t] = tf_keep(k0, k1, (u32)(j0 + t)) ? o[t] * s : 0.0f;
    *(uint2*)(g_a + (size_t)row * DD + c) = pack_h4(o);
}

// ---------------- fused aggregate + epilogue (fp16 y gather) ----------------
template<bool LAST>
__global__ __launch_bounds__(128)
void k_agg(const float* __restrict__ bias, u32 dk0, u32 dk1,
           float* __restrict__ outp) {
    const int n = blockIdx.x;
    const int c = threadIdx.x << 2;
    const int beg = g_roff[n];
    const int end = g_roff[n + 1];
    float4 acc = make_float4(0.f, 0.f, 0.f, 0.f);
    int i = beg;
    for (; i + 3 < end; i += 4) {
        int s0 = g_esrc[i],     s1 = g_esrc[i + 1];
        int s2 = g_esrc[i + 2], s3 = g_esrc[i + 3];
        float w0 = g_eew[i],     w1 = g_eew[i + 1];
        float w2 = g_eew[i + 2], w3 = g_eew[i + 3];
        uint2 u0 = *(const uint2*)(g_y + (size_t)s0 * DD + c);
        uint2 u1 = *(const uint2*)(g_y + (size_t)s1 * DD + c);
        uint2 u2 = *(const uint2*)(g_y + (size_t)s2 * DD + c);
        uint2 u3 = *(const uint2*)(g_y + (size_t)s3 * DD + c);
        float2 a0 = __half22float2(*(__half2*)&u0.x), b0 = __half22float2(*(__half2*)&u0.y);
        float2 a1 = __half22float2(*(__half2*)&u1.x), b1 = __half22float2(*(__half2*)&u1.y);
        float2 a2 = __half22float2(*(__half2*)&u2.x), b2 = __half22float2(*(__half2*)&u2.y);
        float2 a3 = __half22float2(*(__half2*)&u3.x), b3 = __half22float2(*(__half2*)&u3.y);
        acc.x += a0.x * w0 + a1.x * w1 + a2.x * w2 + a3.x * w3;
        acc.y += a0.y * w0 + a1.y * w1 + a2.y * w2 + a3.y * w3;
        acc.z += b0.x * w0 + b1.x * w1 + b2.x * w2 + b3.x * w3;
        acc.w += b0.y * w0 + b1.y * w1 + b2.y * w2 + b3.y * w3;
    }
    for (; i < end; ++i) {
        int s0 = g_esrc[i];
        float w0 = g_eew[i];
        uint2 u0 = *(const uint2*)(g_y + (size_t)s0 * DD + c);
        float2 a0 = __half22float2(*(__half2*)&u0.x), b0 = __half22float2(*(__half2*)&u0.y);
        acc.x += a0.x * w0; acc.y += a0.y * w0;
        acc.z += b0.x * w0; acc.w += b0.y * w0;
    }
    const float s = g_idi[n];
    float4 bv = *(const float4*)(bias + c);
    float o[4];
    o[0] = acc.x * s + bv.x;
    o[1] = acc.y * s + bv.y;
    o[2] = acc.z * s + bv.z;
    o[3] = acc.w * s + bv.w;
    if (LAST) {
        *(float4*)(outp + (size_t)n * DD + c) = make_float4(o[0], o[1], o[2], o[3]);
    } else {
        const float dsc = 1.25f * g_ido[n];
        const u32 jb = (u32)n * DD + (u32)c;
#pragma unroll
        for (int t = 0; t < 4; ++t) {
            float v = o[t] > 0.f ? o[t] : expm1f(o[t]);
            o[t] = tf_keep(dk0, dk1, jb + t) ? v * dsc : 0.0f;
        }
        *(uint2*)(g_a + (size_t)n * DD + c) = pack_h4(o);
    }
}

// ---------------- HMMA fp16 W-split GEMM: g_y = A @ (Wthi+Wtlo)^T -----------
// A single fp16, W split fp16 hi+lo -> 2 MMAs per tile.
// CTA tile 128x64, 8 warps 4x2 (warp tile 32x32), K chunks of 16,
// 4-stage cp.async pipeline, 3 CTAs/SM. Epilogue writes fp16 y.
#define STG_BYTES 12288         /* A 128*48 + W 2*64*48 */
#define GEMM_DSMEM (4 * STG_BYTES)

__global__ __launch_bounds__(256, 3)
void k_gemm_mma(int layer) {
    extern __shared__ char dsm[];
    const u32 sb = smem_u32(dsm);

    const int t = threadIdx.x;
    const int lane = t & 31;
    const int wid = t >> 5;
    const int wm = wid & 3;         // 0..3 -> m offset *32
    const int wn = wid >> 2;        // 0..1 -> n offset *32
    const int g = lane >> 2, tg = lane & 3;
    const int bm = blockIdx.x * 128;
    const int bn = blockIdx.y * 64;

    // ldmatrix B addressing (sB is [n][k], k contiguous -> B^T of col-major operand)
    const int lm = lane & 7;
    const int bq_row = ((lane >> 4) & 1) * 8 + lm;
    const int bq_col = ((lane >> 3) & 1) * 8;

    // cp.async: thread t copies A row ar (half) and one W row (hi or lo tile)
    const int ar = t >> 1, half = t & 1;
    const int br = (t >> 1) & 63, bhl = t >> 7;
    const uint4* pA = (const uint4*)g_a + (size_t)(bm + ar) * 64 + half;
    const __half* wbase = bhl ? g_wtlo : g_wthi;
    const uint4* pB = (const uint4*)(wbase + (size_t)layer * DD * DD)
                      + (size_t)(bn + br) * 64 + half;
    const u32 dA = sb + (u32)(ar * 48 + half * 16);
    const u32 dB = sb + (u32)(6144 + bhl * 3072 + br * 48 + half * 16);

    float acc[2][4][4];
#pragma unroll
    for (int i = 0; i < 2; ++i)
#pragma unroll
        for (int j = 0; j < 4; ++j)
#pragma unroll
            for (int q = 0; q < 4; ++q) acc[i][j][q] = 0.0f;

#define ISSUE(stg, ch) do { \
    u32 _o = (u32)(stg) * STG_BYTES; \
    cp16(dA + _o, pA + (ch) * 2); \
    cp16(dB + _o, pB + (ch) * 2); \
    asm volatile("cp.async.commit_group;" ::: "memory"); \
} while (0)

    ISSUE(0, 0);
    ISSUE(1, 1);
    ISSUE(2, 2);

    const int NCH = DD / 16;   // 32
    for (int ch = 0; ch < NCH; ++ch) {
        const int stg = ch & 3;
        asm volatile("cp.async.wait_group 2;" ::: "memory");
        __syncthreads();
        if (ch + 3 < NCH) {
            ISSUE((ch + 3) & 3, ch + 3);
        } else {
            asm volatile("cp.async.commit_group;" ::: "memory");
        }

        const u32 so = sb + (u32)stg * STG_BYTES;
        const u32 bo = so + 6144;

        // B fragments: 2 ldmatrix.x4 (hi, lo), each covering 4 n-tiles of 8
        u32 bh0[4], bh1[4], bl0[4], bl1[4];
#pragma unroll
        for (int p = 0; p < 2; ++p) {
            const int nrow = wn * 32 + p * 16 + bq_row;
            u32 r0, r1, r2, r3;
            ldsm4(r0, r1, r2, r3, bo + (u32)(nrow * 48 + bq_col * 2));
            bh0[p * 2 + 0] = r0; bh1[p * 2 + 0] = r1;
            bh0[p * 2 + 1] = r2; bh1[p * 2 + 1] = r3;
            ldsm4(r0, r1, r2, r3, bo + (u32)(3072 + nrow * 48 + bq_col * 2));
            bl0[p * 2 + 0] = r0; bl1[p * 2 + 0] = r1;
            bl0[p * 2 + 1] = r2; bl1[p * 2 + 1] = r3;
        }
#pragma unroll
        for (int mt = 0; mt < 2; ++mt) {
            const int arow = wm * 32 + mt * 16 + (lane & 15);
            const int acol = (lane >> 4) * 8;
            u32 a0, a1, a2, a3;
            ldsm4(a0, a1, a2, a3, so + (u32)(arow * 48 + acol * 2));
#pragma unroll
            for (int nt = 0; nt < 4; ++nt) {
                mma_fp16(acc[mt][nt][0], acc[mt][nt][1], acc[mt][nt][2], acc[mt][nt][3],
                         a0, a1, a2, a3, bh0[nt], bh1[nt]);
                mma_fp16(acc[mt][nt][0], acc[mt][nt][1], acc[mt][nt][2], acc[mt][nt][3],
                         a0, a1, a2, a3, bl0[nt], bl1[nt]);
            }
        }
    }
#undef ISSUE

    // epilogue: write fp16 y
#pragma unroll
    for (int mt = 0; mt < 2; ++mt) {
#pragma unroll
        for (int hm = 0; hm < 2; ++hm) {
            const int row = bm + wm * 32 + mt * 16 + g + hm * 8;
            if (row < NN) {
#pragma unroll
                for (int nt = 0; nt < 4; ++nt) {
                    const int col = bn + wn * 32 + nt * 8 + 2 * tg;
                    __half2 hv = __floats2half2_rn(acc[mt][nt][hm * 2 + 0],
                                                   acc[mt][nt][hm * 2 + 1]);
                    *(u32*)&g_y[(size_t)row * DD + col] = *(u32*)&hv;
                }
            }
        }
    }
}

// ---------------- launch ----------------------------------------------------
extern "C" void kernel_launch(void* const* d_in, const int* in_sizes, int n_in,
                              void* d_out, int out_size) {
    (void)in_sizes; (void)n_in; (void)out_size;
    const float* h   = (const float*)d_in[0];
    const int*   src = (const int*)  d_in[1];
    const int*   dst = (const int*)  d_in[2];
    const float* ew  = (const float*)d_in[3];
    const float* W0  = (const float*)d_in[4];
    const float* b0  = (const float*)d_in[5];
    const float* W1  = (const float*)d_in[6];
    const float* b1  = (const float*)d_in[7];
    const float* W2  = (const float*)d_in[8];
    const float* b2  = (const float*)d_in[9];
    float* out = (float*)d_out;

    cudaFuncSetAttribute(k_gemm_mma, cudaFuncAttributeMaxDynamicSharedMemorySize,
                         GEMM_DSMEM);

    const int TB = 256;
    dim3 gemm_grid(MPAD / 128, DD / 64);             // 79 x 8 = 632
    const int drop_blocks = (ND / 4 + TB - 1) / TB;  // 5000

    // 1: zero degrees
    k_zero_deg<<<(NPAD2 + TB - 1) / TB, TB>>>();
    // 2: degree count + weight transpose/split (fused)
    k_setup<<<CNT_BLOCKS + 768, TB>>>(src, dst, W0, W1, W2);
    // 3: layer-0 dropout + src-norm -> fp16 (inline rsqrt of deg_out)
    k_drop<<<drop_blocks, TB>>>(h, DK0.a, DK0.b);
    // 4: GEMM layer 0  (ncu capture slot)
    k_gemm_mma<<<gemm_grid, TB, GEMM_DSMEM>>>(0);
    // 5-6: CSR scan + fill (independent of GEMM; fills pipeline bubble)
    k_scan<<<1, 1024>>>();
    k_fill<<<(EE + TB - 1) / TB, TB>>>(src, dst, ew);
    // 7: aggregate + epilogue (ELU + DK1 dropout -> fp16)
    k_agg<false><<<NN, 128>>>(b0, DK1.a, DK1.b, nullptr);
    // layer 1
    k_gemm_mma<<<gemm_grid, TB, GEMM_DSMEM>>>(1);
    k_agg<false><<<NN, 128>>>(b1, DK2.a, DK2.b, nullptr);
    // layer 2 (final: agg + bias -> d_out)
    k_gemm_mma<<<gemm_grid, TB, GEMM_DSMEM>>>(2);
    k_agg<true><<<NN, 128>>>(b2, 0u, 0u, out);
}

// round 17
// speedup vs baseline: 1.0959x; 1.0959x over previous
#include <cuda_runtime.h>
#include <cuda_bf16.h>
#include <cuda_fp16.h>
#include <math.h>
#include <stdint.h>

typedef unsigned int u32;
typedef unsigned long long u64;

#define NN 10000
#define NPAD2 10240           /* padded degree array for int2 scan loads */
#define EE 160000
#define DD 512
#define ND (NN * DD)          /* 5,120,000 */
#define MPAD 10112            /* 79 * 128 */

// ---------------- scratch (static device globals: allocation-free) ----------
__device__ __align__(16) __half g_y[ND];               // y = z @ W (fp16)
__device__ __align__(16) __half g_a[MPAD * DD];        // GEMM input, fp16 (padded rows stay 0)
__device__ __align__(16) __half g_wthi[3 * DD * DD];   // W^T fp16 hi, per layer
__device__ __align__(16) __half g_wtlo[3 * DD * DD];   // W^T fp16 lo (residual)
__device__ float g_ido[NN];
__device__ float g_idi[NN];
__device__ int   g_dego[NN];
__device__ __align__(16) int g_degi[NPAD2];
__device__ int   g_roff[NN + 1];
__device__ int   g_cur[NN];
__device__ int   g_esrc[EE];
__device__ float g_eew[EE];

// ---------------- JAX-compatible threefry2x32 (partitionable) ---------------
struct U2 { u32 a, b; };
constexpr u32 rotl_c(u32 v, int r) { return (v << r) | (v >> (32 - r)); }
constexpr U2 tf_host(u32 k0, u32 k1, u32 x0, u32 x1) {
    u32 ks2 = 0x1BD11BDAu ^ k0 ^ k1;
    x0 += k0; x1 += k1;
    const int R0[4] = {13, 15, 26, 6};
    const int R1[4] = {17, 29, 16, 24};
    for (int g = 0; g < 5; ++g) {
        for (int i = 0; i < 4; ++i) {
            int r = (g & 1) ? R1[i] : R0[i];
            x0 += x1; x1 = rotl_c(x1, r); x1 ^= x0;
        }
        switch (g) {
            case 0: x0 += k1;  x1 += ks2 + 1u; break;
            case 1: x0 += ks2; x1 += k0  + 2u; break;
            case 2: x0 += k0;  x1 += k1  + 3u; break;
            case 3: x0 += k1;  x1 += ks2 + 4u; break;
            default: x0 += ks2; x1 += k0 + 5u; break;
        }
    }
    return U2{x0, x1};
}
constexpr U2 DK0 = tf_host(0u, 42u, 0u, 0u);
constexpr U2 DK1 = tf_host(0u, 42u, 0u, 1u);
constexpr U2 DK2 = tf_host(0u, 42u, 0u, 2u);

__device__ __forceinline__ void tf_dev(u32 k0, u32 k1, u32& x0, u32& x1) {
    u32 ks2 = 0x1BD11BDAu ^ k0 ^ k1;
    x0 += k0; x1 += k1;
#define TFR(r) { x0 += x1; x1 = (x1 << (r)) | (x1 >> (32 - (r))); x1 ^= x0; }
    TFR(13) TFR(15) TFR(26) TFR(6)   x0 += k1;  x1 += ks2 + 1u;
    TFR(17) TFR(29) TFR(16) TFR(24)  x0 += ks2; x1 += k0  + 2u;
    TFR(13) TFR(15) TFR(26) TFR(6)   x0 += k0;  x1 += k1  + 3u;
    TFR(17) TFR(29) TFR(16) TFR(24)  x0 += k1;  x1 += ks2 + 4u;
    TFR(13) TFR(15) TFR(26) TFR(6)   x0 += ks2; x1 += k0  + 5u;
#undef TFR
}

__device__ __forceinline__ bool tf_keep(u32 k0, u32 k1, u32 j) {
    u32 x0 = 0u, x1 = j;
    tf_dev(k0, k1, x0, x1);
    u32 bits = x0 ^ x1;
    float u = __uint_as_float((bits >> 9) | 0x3f800000u) - 1.0f;
    return u < 0.8f;
}

// pack 4 floats -> 4 fp16 in a uint2
__device__ __forceinline__ uint2 pack_h4(const float* o) {
    __half2 p01 = __floats2half2_rn(o[0], o[1]);
    __half2 p23 = __floats2half2_rn(o[2], o[3]);
    uint2 u;
    u.x = *(u32*)&p01; u.y = *(u32*)&p23;
    return u;
}

// ---------------- mma.sync helpers (family-compatible, no 'a' features) -----
__device__ __forceinline__ u32 smem_u32(const void* p) {
    u32 a;
    asm("{ .reg .u64 t; cvta.to.shared.u64 t, %1; cvt.u32.u64 %0, t; }" : "=r"(a) : "l"(p));
    return a;
}
__device__ __forceinline__ void ldsm4(u32& r0, u32& r1, u32& r2, u32& r3, u32 addr) {
    asm volatile("ldmatrix.sync.aligned.m8n8.x4.shared.b16 {%0,%1,%2,%3}, [%4];"
                 : "=r"(r0), "=r"(r1), "=r"(r2), "=r"(r3) : "r"(addr));
}
__device__ __forceinline__ void mma_fp16(float& c0, float& c1, float& c2, float& c3,
                                         u32 a0, u32 a1, u32 a2, u32 a3,
                                         u32 b0, u32 b1) {
    asm volatile(
        "mma.sync.aligned.m16n8k16.row.col.f32.f16.f16.f32 "
        "{%0,%1,%2,%3}, {%4,%5,%6,%7}, {%8,%9}, {%0,%1,%2,%3};"
        : "+f"(c0), "+f"(c1), "+f"(c2), "+f"(c3)
        : "r"(a0), "r"(a1), "r"(a2), "r"(a3), "r"(b0), "r"(b1));
}
__device__ __forceinline__ void cp16(u32 smem_dst, const void* gptr) {
    asm volatile("cp.async.cg.shared.global [%0], [%1], 16;"
                 :: "r"(smem_dst), "l"(gptr) : "memory");
}

// ---------------- degree + CSR build ---------------------------------------
__global__ void k_zero_deg() {
    int i = blockIdx.x * blockDim.x + threadIdx.x;
    if (i < NN) g_dego[i] = 0;
    if (i < NPAD2) g_degi[i] = 0;
}

// fused: degree count (blocks 0..624) + weight transpose/split (blocks 625..1392)
#define CNT_BLOCKS 625
__global__ void k_setup(const int* __restrict__ src, const int* __restrict__ dst,
                        const float* __restrict__ W0, const float* __restrict__ W1,
                        const float* __restrict__ W2) {
    if (blockIdx.x < CNT_BLOCKS) {
        int e = blockIdx.x * blockDim.x + threadIdx.x;
        if (e < EE) {
            atomicAdd(&g_dego[src[e]], 1);
            atomicAdd(&g_degi[dst[e]], 1);
        }
        return;
    }
    __shared__ float tile[32][33];
    const int bid = blockIdx.x - CNT_BLOCKS;
    const int L = bid >> 8;                    // 0..2
    const int tix = bid & 255;
    const int bx = (tix & 15) * 32, by = (tix >> 4) * 32;
    const float* __restrict__ W = (L == 0) ? W0 : ((L == 1) ? W1 : W2);
    __half* __restrict__ TH = g_wthi + (size_t)L * DD * DD;
    __half* __restrict__ TL = g_wtlo + (size_t)L * DD * DD;
    const int tx = threadIdx.x & 31, ty = threadIdx.x >> 5;   // 32 x 8
#pragma unroll
    for (int i = 0; i < 32; i += 8)
        tile[ty + i][tx] = W[(size_t)(by + ty + i) * DD + bx + tx];
    __syncthreads();
#pragma unroll
    for (int i = 0; i < 32; i += 8) {
        float v = tile[tx][ty + i];
        __half h = __float2half_rn(v);
        float lo = v - __half2float(h);
        TH[(size_t)(bx + ty + i) * DD + by + tx] = h;
        TL[(size_t)(bx + ty + i) * DD + by + tx] = __float2half_rn(lo);
    }
}

// pure exclusive prefix sum of g_degi -> g_roff / g_cur
__global__ void k_scan() {
    const int t = threadIdx.x;
    const int2* p = (const int2*)g_degi + t * 5;
    int2 d0 = p[0], d1 = p[1], d2 = p[2], d3 = p[3], d4 = p[4];
    int vals[10] = {d0.x, d0.y, d1.x, d1.y, d2.x, d2.y, d3.x, d3.y, d4.x, d4.y};
    int loc[10], sum = 0;
#pragma unroll
    for (int i = 0; i < 10; ++i) { loc[i] = sum; sum += vals[i]; }
    int lane = t & 31, w = t >> 5;
    int inc = sum;
#pragma unroll
    for (int o = 1; o < 32; o <<= 1) {
        int x = __shfl_up_sync(0xFFFFFFFFu, inc, o);
        if (lane >= o) inc += x;
    }
    __shared__ int ws[32];
    if (lane == 31) ws[w] = inc;
    __syncthreads();
    if (w == 0) {
        int x = ws[lane];
#pragma unroll
        for (int o = 1; o < 32; o <<= 1) {
            int y = __shfl_up_sync(0xFFFFFFFFu, x, o);
            if (lane >= o) x += y;
        }
        ws[lane] = x;
    }
    __syncthreads();
    int excl = inc - sum + (w ? ws[w - 1] : 0);
#pragma unroll
    for (int i = 0; i < 10; ++i) {
        int idx = t * 10 + i;
        if (idx < NN) { int o = excl + loc[i]; g_roff[idx] = o; g_cur[idx] = o; }
    }
    if (t == 0) g_roff[NN] = ws[31];
}

// CSR fill + grid-wide rsqrt of degrees
__global__ void k_fill(const int* __restrict__ src, const int* __restrict__ dst,
                       const float* __restrict__ ew) {
    int e = blockIdx.x * blockDim.x + threadIdx.x;
    if (e < NN) {
        g_ido[e] = rsqrtf(fmaxf((float)g_dego[e], 1.0f));
        g_idi[e] = rsqrtf(fmaxf((float)g_degi[e], 1.0f));
    }
    if (e < EE) {
        int pos = atomicAdd(&g_cur[dst[e]], 1);
        g_esrc[pos] = src[e];
        g_eew[pos] = ew[e];
    }
}

// ---------------- layer-0: dropout(h)*do^-0.5 -> fp16 -----------------------
__global__ void k_drop(const float* __restrict__ xin, u32 k0, u32 k1) {
    int q = blockIdx.x * blockDim.x + threadIdx.x;
    if (q >= ND / 4) return;
    int j0 = q << 2;
    int row = j0 >> 9, c = j0 & 511;
    float4 v = *(const float4*)(xin + j0);
    float s = rsqrtf(fmaxf((float)g_dego[row], 1.0f)) * 1.25f;
    float o[4] = {v.x, v.y, v.z, v.w};
#pragma unroll
    for (int t = 0; t < 4; ++t)
        o[t] = tf_keep(k0, k1, (u32)(j0 + t)) ? o[t] * s : 0.0f;
    *(uint2*)(g_a + (size_t)row * DD + c) = pack_h4(o);
}

// ---------------- fused aggregate + epilogue --------------------------------
// 64 threads per node, 8 fp16 columns (one 16B load) per thread per edge:
// halves the gather load count vs 128x4 (LDG-issue-rate bound, per R16 evidence).
template<bool LAST>
__global__ __launch_bounds__(64)
void k_agg(const float* __restrict__ bias, u32 dk0, u32 dk1,
           float* __restrict__ outp) {
    const int n = blockIdx.x;
    const int c = threadIdx.x << 3;       // 8 columns
    const int beg = g_roff[n];
    const int end = g_roff[n + 1];
    float acc[8];
#pragma unroll
    for (int j = 0; j < 8; ++j) acc[j] = 0.0f;

    int i = beg;
    for (; i + 3 < end; i += 4) {
#pragma unroll
        for (int e = 0; e < 4; ++e) {
            int sN = g_esrc[i + e];
            float wN = g_eew[i + e];
            uint4 u = *(const uint4*)(g_y + (size_t)sN * DD + c);
            float2 f0 = __half22float2(*(__half2*)&u.x);
            float2 f1 = __half22float2(*(__half2*)&u.y);
            float2 f2 = __half22float2(*(__half2*)&u.z);
            float2 f3 = __half22float2(*(__half2*)&u.w);
            acc[0] += f0.x * wN; acc[1] += f0.y * wN;
            acc[2] += f1.x * wN; acc[3] += f1.y * wN;
            acc[4] += f2.x * wN; acc[5] += f2.y * wN;
            acc[6] += f3.x * wN; acc[7] += f3.y * wN;
        }
    }
    for (; i < end; ++i) {
        int sN = g_esrc[i];
        float wN = g_eew[i];
        uint4 u = *(const uint4*)(g_y + (size_t)sN * DD + c);
        float2 f0 = __half22float2(*(__half2*)&u.x);
        float2 f1 = __half22float2(*(__half2*)&u.y);
        float2 f2 = __half22float2(*(__half2*)&u.z);
        float2 f3 = __half22float2(*(__half2*)&u.w);
        acc[0] += f0.x * wN; acc[1] += f0.y * wN;
        acc[2] += f1.x * wN; acc[3] += f1.y * wN;
        acc[4] += f2.x * wN; acc[5] += f2.y * wN;
        acc[6] += f3.x * wN; acc[7] += f3.y * wN;
    }

    const float s = g_idi[n];
    float4 bv0 = *(const float4*)(bias + c);
    float4 bv1 = *(const float4*)(bias + c + 4);
    float o[8];
    o[0] = acc[0] * s + bv0.x; o[1] = acc[1] * s + bv0.y;
    o[2] = acc[2] * s + bv0.z; o[3] = acc[3] * s + bv0.w;
    o[4] = acc[4] * s + bv1.x; o[5] = acc[5] * s + bv1.y;
    o[6] = acc[6] * s + bv1.z; o[7] = acc[7] * s + bv1.w;

    if (LAST) {
        float* op = outp + (size_t)n * DD + c;
        *(float4*)(op)     = make_float4(o[0], o[1], o[2], o[3]);
        *(float4*)(op + 4) = make_float4(o[4], o[5], o[6], o[7]);
    } else {
        const float dsc = 1.25f * g_ido[n];
        const u32 jb = (u32)n * DD + (u32)c;
#pragma unroll
        for (int t = 0; t < 8; ++t) {
            float v = o[t] > 0.f ? o[t] : expm1f(o[t]);
            o[t] = tf_keep(dk0, dk1, jb + t) ? v * dsc : 0.0f;
        }
        uint2 u0 = pack_h4(o);
        uint2 u1 = pack_h4(o + 4);
        uint4 uu; uu.x = u0.x; uu.y = u0.y; uu.z = u1.x; uu.w = u1.y;
        *(uint4*)(g_a + (size_t)n * DD + c) = uu;
    }
}

// ---------------- HMMA fp16 W-split GEMM: g_y = A @ (Wthi+Wtlo)^T -----------
// A single fp16, W split fp16 hi+lo -> 2 MMAs per tile.
// CTA tile 128x64, 8 warps 4x2 (warp tile 32x32), K chunks of 16,
// 4-stage cp.async pipeline, 3 CTAs/SM. Epilogue writes fp16 y.
#define STG_BYTES 12288         /* A 128*48 + W 2*64*48 */
#define GEMM_DSMEM (4 * STG_BYTES)

__global__ __launch_bounds__(256, 3)
void k_gemm_mma(int layer) {
    extern __shared__ char dsm[];
    const u32 sb = smem_u32(dsm);

    const int t = threadIdx.x;
    const int lane = t & 31;
    const int wid = t >> 5;
    const int wm = wid & 3;         // 0..3 -> m offset *32
    const int wn = wid >> 2;        // 0..1 -> n offset *32
    const int g = lane >> 2, tg = lane & 3;
    const int bm = blockIdx.x * 128;
    const int bn = blockIdx.y * 64;

    // ldmatrix B addressing (sB is [n][k], k contiguous -> B^T of col-major operand)
    const int lm = lane & 7;
    const int bq_row = ((lane >> 4) & 1) * 8 + lm;
    const int bq_col = ((lane >> 3) & 1) * 8;

    // cp.async: thread t copies A row ar (half) and one W row (hi or lo tile)
    const int ar = t >> 1, half = t & 1;
    const int br = (t >> 1) & 63, bhl = t >> 7;
    const uint4* pA = (const uint4*)g_a + (size_t)(bm + ar) * 64 + half;
    const __half* wbase = bhl ? g_wtlo : g_wthi;
    const uint4* pB = (const uint4*)(wbase + (size_t)layer * DD * DD)
                      + (size_t)(bn + br) * 64 + half;
    const u32 dA = sb + (u32)(ar * 48 + half * 16);
    const u32 dB = sb + (u32)(6144 + bhl * 3072 + br * 48 + half * 16);

    float acc[2][4][4];
#pragma unroll
    for (int i = 0; i < 2; ++i)
#pragma unroll
        for (int j = 0; j < 4; ++j)
#pragma unroll
            for (int q = 0; q < 4; ++q) acc[i][j][q] = 0.0f;

#define ISSUE(stg, ch) do { \
    u32 _o = (u32)(stg) * STG_BYTES; \
    cp16(dA + _o, pA + (ch) * 2); \
    cp16(dB + _o, pB + (ch) * 2); \
    asm volatile("cp.async.commit_group;" ::: "memory"); \
} while (0)

    ISSUE(0, 0);
    ISSUE(1, 1);
    ISSUE(2, 2);

    const int NCH = DD / 16;   // 32
    for (int ch = 0; ch < NCH; ++ch) {
        const int stg = ch & 3;
        asm volatile("cp.async.wait_group 2;" ::: "memory");
        __syncthreads();
        if (ch + 3 < NCH) {
            ISSUE((ch + 3) & 3, ch + 3);
        } else {
            asm volatile("cp.async.commit_group;" ::: "memory");
        }

        const u32 so = sb + (u32)stg * STG_BYTES;
        const u32 bo = so + 6144;

        // B fragments: 2 ldmatrix.x4 (hi, lo), each covering 4 n-tiles of 8
        u32 bh0[4], bh1[4], bl0[4], bl1[4];
#pragma unroll
        for (int p = 0; p < 2; ++p) {
            const int nrow = wn * 32 + p * 16 + bq_row;
            u32 r0, r1, r2, r3;
            ldsm4(r0, r1, r2, r3, bo + (u32)(nrow * 48 + bq_col * 2));
            bh0[p * 2 + 0] = r0; bh1[p * 2 + 0] = r1;
            bh0[p * 2 + 1] = r2; bh1[p * 2 + 1] = r3;
            ldsm4(r0, r1, r2, r3, bo + (u32)(3072 + nrow * 48 + bq_col * 2));
            bl0[p * 2 + 0] = r0; bl1[p * 2 + 0] = r1;
            bl0[p * 2 + 1] = r2; bl1[p * 2 + 1] = r3;
        }
#pragma unroll
        for (int mt = 0; mt < 2; ++mt) {
            const int arow = wm * 32 + mt * 16 + (lane & 15);
            const int acol = (lane >> 4) * 8;
            u32 a0, a1, a2, a3;
            ldsm4(a0, a1, a2, a3, so + (u32)(arow * 48 + acol * 2));
#pragma unroll
            for (int nt = 0; nt < 4; ++nt) {
                mma_fp16(acc[mt][nt][0], acc[mt][nt][1], acc[mt][nt][2], acc[mt][nt][3],
                         a0, a1, a2, a3, bh0[nt], bh1[nt]);
                mma_fp16(acc[mt][nt][0], acc[mt][nt][1], acc[mt][nt][2], acc[mt][nt][3],
                         a0, a1, a2, a3, bl0[nt], bl1[nt]);
            }
        }
    }
#undef ISSUE

    // epilogue: write fp16 y
#pragma unroll
    for (int mt = 0; mt < 2; ++mt) {
#pragma unroll
        for (int hm = 0; hm < 2; ++hm) {
            const int row = bm + wm * 32 + mt * 16 + g + hm * 8;
            if (row < NN) {
#pragma unroll
                for (int nt = 0; nt < 4; ++nt) {
                    const int col = bn + wn * 32 + nt * 8 + 2 * tg;
                    __half2 hv = __floats2half2_rn(acc[mt][nt][hm * 2 + 0],
                                                   acc[mt][nt][hm * 2 + 1]);
                    *(u32*)&g_y[(size_t)row * DD + col] = *(u32*)&hv;
                }
            }
        }
    }
}

// ---------------- launch ----------------------------------------------------
extern "C" void kernel_launch(void* const* d_in, const int* in_sizes, int n_in,
                              void* d_out, int out_size) {
    (void)in_sizes; (void)n_in; (void)out_size;
    const float* h   = (const float*)d_in[0];
    const int*   src = (const int*)  d_in[1];
    const int*   dst = (const int*)  d_in[2];
    const float* ew  = (const float*)d_in[3];
    const float* W0  = (const float*)d_in[4];
    const float* b0  = (const float*)d_in[5];
    const float* W1  = (const float*)d_in[6];
    const float* b1  = (const float*)d_in[7];
    const float* W2  = (const float*)d_in[8];
    const float* b2  = (const float*)d_in[9];
    float* out = (float*)d_out;

    cudaFuncSetAttribute(k_gemm_mma, cudaFuncAttributeMaxDynamicSharedMemorySize,
                         GEMM_DSMEM);

    const int TB = 256;
    dim3 gemm_grid(MPAD / 128, DD / 64);             // 79 x 8 = 632
    const int drop_blocks = (ND / 4 + TB - 1) / TB;  // 5000

    // 1: zero degrees
    k_zero_deg<<<(NPAD2 + TB - 1) / TB, TB>>>();
    // 2: degree count + weight transpose/split (fused)
    k_setup<<<CNT_BLOCKS + 768, TB>>>(src, dst, W0, W1, W2);
    // 3: layer-0 dropout + src-norm -> fp16 (inline rsqrt of deg_out)
    k_drop<<<drop_blocks, TB>>>(h, DK0.a, DK0.b);
    // 4: GEMM layer 0  (ncu capture slot)
    k_gemm_mma<<<gemm_grid, TB, GEMM_DSMEM>>>(0);
    // 5-6: CSR scan + fill (independent of GEMM; fills pipeline bubble)
    k_scan<<<1, 1024>>>();
    k_fill<<<(EE + TB - 1) / TB, TB>>>(src, dst, ew);
    // 7: aggregate + epilogue (ELU + DK1 dropout -> fp16)
    k_agg<false><<<NN, 64>>>(b0, DK1.a, DK1.b, nullptr);
    // layer 1
    k_gemm_mma<<<gemm_grid, TB, GEMM_DSMEM>>>(1);
    k_agg<false><<<NN, 64>>>(b1, DK2.a, DK2.b, nullptr);
    // layer 2 (final: agg + bias -> d_out)
    k_gemm_mma<<<gemm_grid, TB, GEMM_DSMEM>>>(2);
    k_agg<true><<<NN, 64>>>(b2, 0u, 0u, out);
}